// round 3
// baseline (speedup 1.0000x reference)
#include <cuda_runtime.h>
#include <cstdint>

#define NN 50000
#define DD 64

// Scratch (device globals; no allocations allowed)
__device__ __align__(16) float g_agg[NN * DD];   // 12.8 MB aggregation buffer
__device__ float g_cnt[NN];                      // in-degree counts (float)
__device__ __align__(16) float g_h[NN * DD];     // layer-0 output
__device__ __align__(16) float g_Wt0[2 * DD * DD]; // [k][j]: k<64 -> Wl0[j][k], k>=64 -> Wr0[j][k-64]
__device__ __align__(16) float g_Wt1[2 * DD * DD];
__device__ int g_is64;                           // edge-index dtype flag

// Detect whether edge_index is int64 or int32. Valid indices are < 50000,
// so a genuine int64 entry has hi-word == 0. int32 data reinterpreted as
// int64 puts a random index in the hi-word (P(zero x8) ~ (1/50000)^8).
__global__ void detect_dtype(const long long* __restrict__ ei) {
    long long acc = 0;
#pragma unroll
    for (int i = 0; i < 8; i++) acc |= (ei[i] >> 32);
    g_is64 = (acc == 0) ? 1 : 0;
}

// Pre-transpose weights into B[k][j] layout so the GEMM loads them coalesced
// and stores to shared with zero bank conflicts.
__global__ void prep_weights(const float* __restrict__ Wl0, const float* __restrict__ Wr0,
                             const float* __restrict__ Wl1, const float* __restrict__ Wr1) {
    int i = blockIdx.x * blockDim.x + threadIdx.x;
    if (i >= 2 * DD * DD) return;
    int k = i >> 6;
    int j = i & 63;
    g_Wt0[i] = (k < DD) ? Wl0[j * DD + k] : Wr0[j * DD + (k - DD)];
    g_Wt1[i] = (k < DD) ? Wl1[j * DD + k] : Wr1[j * DD + (k - DD)];
}

__global__ void zero_kernel(int alsoCnt) {
    int i = blockIdx.x * blockDim.x + threadIdx.x;
    if (i < NN * DD / 4)
        reinterpret_cast<float4*>(g_agg)[i] = make_float4(0.f, 0.f, 0.f, 0.f);
    if (alsoCnt && i < NN)
        g_cnt[i] = 0.f;
}

// One edge per 16 threads; each thread moves one float4 (16B) of the 256B row.
// Vector reduction (red.global.add.v4.f32, sm_90+) with explicit cvta.to.global.
__global__ void scatter_kernel(const float* __restrict__ x,
                               const void* __restrict__ ei_raw,
                               int E, int useH, int doCount) {
    int gid = blockIdx.x * blockDim.x + threadIdx.x;
    int e = gid >> 4;
    if (e >= E) return;
    int lane = gid & 15;
    const float* xin = useH ? g_h : x;

    int s, d;
    if (g_is64) {
        const long long* ei = (const long long*)ei_raw;
        s = (int)ei[e];
        d = (int)ei[E + e];
    } else {
        const int* ei = (const int*)ei_raw;
        s = ei[e];
        d = ei[E + e];
    }

    float4 v = reinterpret_cast<const float4*>(xin + (size_t)s * DD)[lane];
    float* dst = g_agg + (size_t)d * DD + lane * 4;
    asm volatile(
        "{\n\t"
        ".reg .b64 pg;\n\t"
        "cvta.to.global.u64 pg, %0;\n\t"
        "red.global.add.v4.f32 [pg], {%1,%2,%3,%4};\n\t"
        "}"
        :: "l"(dst), "f"(v.x), "f"(v.y), "f"(v.z), "f"(v.w)
        : "memory");
    if (doCount && lane == 0)
        atomicAdd(&g_cnt[d], 1.0f);
}

// Fused: agg-normalize + C[64 nodes][64 out] = A[64][128] * B[128][64] + bias (+ ReLU)
// A = [agg/cnt | xin], B = [Wl^T ; Wr^T] (pre-transposed).
// Classic tiled SGEMM: 256 threads, 4x4 register micro-tile, 2 LDS.128 per 16 FMA.
__global__ __launch_bounds__(256) void gemm_combine(const float* __restrict__ x,
                                                    int useH, int useW1,
                                                    const float* __restrict__ bias,
                                                    float* __restrict__ dout,
                                                    int writeH, int doRelu) {
    __shared__ __align__(16) float sA[64 * 64];  // [k][m], k-half at a time
    __shared__ __align__(16) float sB[64 * 64];  // [k][j]
    const float* xin = useH ? g_h : x;
    const float* Wt = useW1 ? g_Wt1 : g_Wt0;
    float* outp = writeH ? g_h : dout;

    int t = threadIdx.x;
    int m0 = blockIdx.x * 64;
    int m = t & 63;          // node within tile (for loading)
    int q = t >> 6;          // 0..3: k-quarter within the 64-k half
    int node = m0 + m;

    int tx = t & 15;         // output-col group (4 cols)
    int ty = t >> 4;         // node group (4 nodes)

    float acc[4][4];
#pragma unroll
    for (int i = 0; i < 4; i++)
#pragma unroll
        for (int j = 0; j < 4; j++) acc[i][j] = 0.f;

    float scale = 1.f;
    if (node < NN) scale = 1.f / fmaxf(g_cnt[node], 1.f);

#pragma unroll
    for (int kt = 0; kt < 2; kt++) {
        // Load B half: 4096 floats = 1024 float4, 4 per thread (coalesced, conflict-free)
        const float4* Bsrc = reinterpret_cast<const float4*>(Wt + kt * 4096);
#pragma unroll
        for (int f = 0; f < 4; f++)
            reinterpret_cast<float4*>(sB)[f * 256 + t] = Bsrc[f * 256 + t];

        // Load A half (transposed into [k][m]): row source = agg (kt=0) or xin (kt=1)
        const float* srcRow = (kt == 0) ? (g_agg + (size_t)node * DD)
                                        : (xin + (size_t)node * DD);
        float sc = (kt == 0) ? scale : 1.f;
        int kbase = q * 16;
#pragma unroll
        for (int f = 0; f < 4; f++) {
            float4 v = make_float4(0.f, 0.f, 0.f, 0.f);
            if (node < NN)
                v = *reinterpret_cast<const float4*>(srcRow + kbase + f * 4);
            v.x *= sc; v.y *= sc; v.z *= sc; v.w *= sc;
            int k = kbase + f * 4;
            // lanes differ in m (consecutive) -> conflict-free scalar stores
            sA[(k + 0) * 64 + m] = v.x;
            sA[(k + 1) * 64 + m] = v.y;
            sA[(k + 2) * 64 + m] = v.z;
            sA[(k + 3) * 64 + m] = v.w;
        }
        __syncthreads();

#pragma unroll 8
        for (int k = 0; k < 64; k++) {
            float4 a = *reinterpret_cast<const float4*>(sA + k * 64 + ty * 4);
            float4 b = *reinterpret_cast<const float4*>(sB + k * 64 + tx * 4);
            acc[0][0] += a.x * b.x; acc[0][1] += a.x * b.y; acc[0][2] += a.x * b.z; acc[0][3] += a.x * b.w;
            acc[1][0] += a.y * b.x; acc[1][1] += a.y * b.y; acc[1][2] += a.y * b.z; acc[1][3] += a.y * b.w;
            acc[2][0] += a.z * b.x; acc[2][1] += a.z * b.y; acc[2][2] += a.z * b.z; acc[2][3] += a.z * b.w;
            acc[3][0] += a.w * b.x; acc[3][1] += a.w * b.y; acc[3][2] += a.w * b.z; acc[3][3] += a.w * b.w;
        }
        __syncthreads();
    }

    float4 bv = *reinterpret_cast<const float4*>(bias + tx * 4);
#pragma unroll
    for (int i = 0; i < 4; i++) {
        int row = m0 + ty * 4 + i;
        if (row >= NN) continue;
        float4 o;
        o.x = acc[i][0] + bv.x;
        o.y = acc[i][1] + bv.y;
        o.z = acc[i][2] + bv.z;
        o.w = acc[i][3] + bv.w;
        if (doRelu) {
            o.x = fmaxf(o.x, 0.f); o.y = fmaxf(o.y, 0.f);
            o.z = fmaxf(o.z, 0.f); o.w = fmaxf(o.w, 0.f);
        }
        *reinterpret_cast<float4*>(outp + (size_t)row * DD + tx * 4) = o;
    }
}

extern "C" void kernel_launch(void* const* d_in, const int* in_sizes, int n_in,
                              void* d_out, int out_size) {
    const float* x        = (const float*)d_in[0];
    const void* ei        = d_in[1];
    const float* Wl0      = (const float*)d_in[2];
    const float* bl0      = (const float*)d_in[3];
    const float* Wr0      = (const float*)d_in[4];
    const float* Wl1      = (const float*)d_in[5];
    const float* bl1      = (const float*)d_in[6];
    const float* Wr1      = (const float*)d_in[7];
    float* out = (float*)d_out;

    int E = in_sizes[1] / 2;

    int zeroBlocks = (NN * DD / 4 + 255) / 256;
    int scatBlocks = (int)(((long long)E * 16 + 255) / 256);
    int gemmBlocks = (NN + 63) / 64;

    detect_dtype<<<1, 1>>>((const long long*)ei);
    prep_weights<<<(2 * DD * DD + 255) / 256, 256>>>(Wl0, Wr0, Wl1, Wr1);

    // Layer 0
    zero_kernel<<<zeroBlocks, 256>>>(1);
    scatter_kernel<<<scatBlocks, 256>>>(x, ei, E, /*useH=*/0, /*doCount=*/1);
    gemm_combine<<<gemmBlocks, 256>>>(x, /*useH=*/0, /*useW1=*/0, bl0, out,
                                      /*writeH=*/1, /*doRelu=*/1);

    // Layer 1
    zero_kernel<<<zeroBlocks, 256>>>(0);
    scatter_kernel<<<scatBlocks, 256>>>(x, ei, E, /*useH=*/1, /*doCount=*/0);
    gemm_combine<<<gemmBlocks, 256>>>(x, /*useH=*/1, /*useW1=*/1, bl1, out,
                                      /*writeH=*/0, /*doRelu=*/0);
}

// round 4
// speedup vs baseline: 1.0535x; 1.0535x over previous
#include <cuda_runtime.h>
#include <cstdint>

#define NN 50000
#define DD 64

// Scratch (device globals; no allocations allowed)
__device__ __align__(16) float g_agg[NN * DD];   // 12.8 MB aggregation buffer
__device__ float g_cnt[NN];                      // in-degree counts (float)
__device__ __align__(16) float g_h[NN * DD];     // layer-0 output
__device__ __align__(16) float g_Wt0[2 * DD * DD]; // [k][j]: k<64 -> Wl0[j][k], k>=64 -> Wr0[j][k-64]
__device__ __align__(16) float g_Wt1[2 * DD * DD];
__device__ int g_is64;                           // edge-index dtype flag

// Detect whether edge_index is int64 or int32. Valid indices are < 50000,
// so a genuine int64 entry has hi-word == 0.
__global__ void detect_dtype(const long long* __restrict__ ei) {
    long long acc = 0;
#pragma unroll
    for (int i = 0; i < 8; i++) acc |= (ei[i] >> 32);
    g_is64 = (acc == 0) ? 1 : 0;
}

__global__ void prep_weights(const float* __restrict__ Wl0, const float* __restrict__ Wr0,
                             const float* __restrict__ Wl1, const float* __restrict__ Wr1) {
    int i = blockIdx.x * blockDim.x + threadIdx.x;
    if (i >= 2 * DD * DD) return;
    int k = i >> 6;
    int j = i & 63;
    g_Wt0[i] = (k < DD) ? Wl0[j * DD + k] : Wr0[j * DD + (k - DD)];
    g_Wt1[i] = (k < DD) ? Wl1[j * DD + k] : Wr1[j * DD + (k - DD)];
}

__global__ void zero_kernel(int alsoCnt) {
    int i = blockIdx.x * blockDim.x + threadIdx.x;
    if (i < NN * DD / 4)
        reinterpret_cast<float4*>(g_agg)[i] = make_float4(0.f, 0.f, 0.f, 0.f);
    if (alsoCnt && i < NN)
        g_cnt[i] = 0.f;
}

__device__ __forceinline__ void red_v4(float* dst, float4 v) {
    asm volatile(
        "{\n\t"
        ".reg .b64 pg;\n\t"
        "cvta.to.global.u64 pg, %0;\n\t"
        "red.global.add.v4.f32 [pg], {%1,%2,%3,%4};\n\t"
        "}"
        :: "l"(dst), "f"(v.x), "f"(v.y), "f"(v.z), "f"(v.w)
        : "memory");
}

// 4 edges per 16-thread group: each thread issues 4 INDEPENDENT gather
// LDG.128s (MLP=4) before its 4 REDs. Index loads are vectorized and
// broadcast across the half-warp. E is assumed divisible by 4 (800000 is);
// tail guard handles the general case per-edge.
#define EPB 4
__global__ void scatter_kernel(const float* __restrict__ x,
                               const void* __restrict__ ei_raw,
                               int E, int useH, int doCount) {
    int gid = blockIdx.x * blockDim.x + threadIdx.x;
    int grp = gid >> 4;
    int lane = gid & 15;
    int e0 = grp * EPB;
    if (e0 >= E) return;
    const float* xin = useH ? g_h : x;

    int s[EPB], d[EPB];
    if (g_is64) {
        const long long* ei = (const long long*)ei_raw;
        if (e0 + EPB <= E && ((e0 & 1) == 0)) {
            longlong2 s01 = *reinterpret_cast<const longlong2*>(ei + e0);
            longlong2 s23 = *reinterpret_cast<const longlong2*>(ei + e0 + 2);
            s[0] = (int)s01.x; s[1] = (int)s01.y; s[2] = (int)s23.x; s[3] = (int)s23.y;
            const long long* eid = ei + E + e0;
            // dst base may be odd-aligned if E is odd; scalar fallback is fine
            if (((size_t)eid & 15) == 0) {
                longlong2 d01 = *reinterpret_cast<const longlong2*>(eid);
                longlong2 d23 = *reinterpret_cast<const longlong2*>(eid + 2);
                d[0] = (int)d01.x; d[1] = (int)d01.y; d[2] = (int)d23.x; d[3] = (int)d23.y;
            } else {
#pragma unroll
                for (int i = 0; i < EPB; i++) d[i] = (int)eid[i];
            }
        } else {
#pragma unroll
            for (int i = 0; i < EPB; i++) {
                int e = min(e0 + i, E - 1);
                s[i] = (int)ei[e]; d[i] = (int)ei[E + e];
            }
        }
    } else {
        const int* ei = (const int*)ei_raw;
        if (e0 + EPB <= E && ((e0 & 3) == 0) && ((E & 3) == 0)) {
            int4 sv = *reinterpret_cast<const int4*>(ei + e0);
            int4 dv = *reinterpret_cast<const int4*>(ei + E + e0);
            s[0] = sv.x; s[1] = sv.y; s[2] = sv.z; s[3] = sv.w;
            d[0] = dv.x; d[1] = dv.y; d[2] = dv.z; d[3] = dv.w;
        } else {
#pragma unroll
            for (int i = 0; i < EPB; i++) {
                int e = min(e0 + i, E - 1);
                s[i] = ei[e]; d[i] = ei[E + e];
            }
        }
    }

    int nvalid = min(EPB, E - e0);

    // Issue all gathers first -> 4 outstanding independent LDG.128
    float4 v[EPB];
#pragma unroll
    for (int i = 0; i < EPB; i++)
        v[i] = __ldg(reinterpret_cast<const float4*>(xin + (size_t)s[i] * DD) + lane);

#pragma unroll
    for (int i = 0; i < EPB; i++)
        if (i < nvalid)
            red_v4(g_agg + (size_t)d[i] * DD + lane * 4, v[i]);

    if (doCount && lane < nvalid)
        atomicAdd(&g_cnt[d[lane]], 1.0f);
}

// Fused: agg-normalize + C[64 nodes][64 out] = A[64][128] * B[128][64] + bias (+ ReLU)
__global__ __launch_bounds__(256) void gemm_combine(const float* __restrict__ x,
                                                    int useH, int useW1,
                                                    const float* __restrict__ bias,
                                                    float* __restrict__ dout,
                                                    int writeH, int doRelu) {
    __shared__ __align__(16) float sA[64 * 64];  // [k][m], k-half at a time
    __shared__ __align__(16) float sB[64 * 64];  // [k][j]
    const float* xin = useH ? g_h : x;
    const float* Wt = useW1 ? g_Wt1 : g_Wt0;
    float* outp = writeH ? g_h : dout;

    int t = threadIdx.x;
    int m0 = blockIdx.x * 64;
    int m = t & 63;
    int q = t >> 6;
    int node = m0 + m;

    int tx = t & 15;
    int ty = t >> 4;

    float acc[4][4];
#pragma unroll
    for (int i = 0; i < 4; i++)
#pragma unroll
        for (int j = 0; j < 4; j++) acc[i][j] = 0.f;

    float scale = 1.f;
    if (node < NN) scale = 1.f / fmaxf(g_cnt[node], 1.f);

#pragma unroll
    for (int kt = 0; kt < 2; kt++) {
        const float4* Bsrc = reinterpret_cast<const float4*>(Wt + kt * 4096);
#pragma unroll
        for (int f = 0; f < 4; f++)
            reinterpret_cast<float4*>(sB)[f * 256 + t] = Bsrc[f * 256 + t];

        const float* srcRow = (kt == 0) ? (g_agg + (size_t)node * DD)
                                        : (xin + (size_t)node * DD);
        float sc = (kt == 0) ? scale : 1.f;
        int kbase = q * 16;
#pragma unroll
        for (int f = 0; f < 4; f++) {
            float4 v = make_float4(0.f, 0.f, 0.f, 0.f);
            if (node < NN)
                v = *reinterpret_cast<const float4*>(srcRow + kbase + f * 4);
            v.x *= sc; v.y *= sc; v.z *= sc; v.w *= sc;
            int k = kbase + f * 4;
            sA[(k + 0) * 64 + m] = v.x;
            sA[(k + 1) * 64 + m] = v.y;
            sA[(k + 2) * 64 + m] = v.z;
            sA[(k + 3) * 64 + m] = v.w;
        }
        __syncthreads();

#pragma unroll 8
        for (int k = 0; k < 64; k++) {
            float4 a = *reinterpret_cast<const float4*>(sA + k * 64 + ty * 4);
            float4 b = *reinterpret_cast<const float4*>(sB + k * 64 + tx * 4);
            acc[0][0] += a.x * b.x; acc[0][1] += a.x * b.y; acc[0][2] += a.x * b.z; acc[0][3] += a.x * b.w;
            acc[1][0] += a.y * b.x; acc[1][1] += a.y * b.y; acc[1][2] += a.y * b.z; acc[1][3] += a.y * b.w;
            acc[2][0] += a.z * b.x; acc[2][1] += a.z * b.y; acc[2][2] += a.z * b.z; acc[2][3] += a.z * b.w;
            acc[3][0] += a.w * b.x; acc[3][1] += a.w * b.y; acc[3][2] += a.w * b.z; acc[3][3] += a.w * b.w;
        }
        __syncthreads();
    }

    float4 bv = *reinterpret_cast<const float4*>(bias + tx * 4);
#pragma unroll
    for (int i = 0; i < 4; i++) {
        int row = m0 + ty * 4 + i;
        if (row >= NN) continue;
        float4 o;
        o.x = acc[i][0] + bv.x;
        o.y = acc[i][1] + bv.y;
        o.z = acc[i][2] + bv.z;
        o.w = acc[i][3] + bv.w;
        if (doRelu) {
            o.x = fmaxf(o.x, 0.f); o.y = fmaxf(o.y, 0.f);
            o.z = fmaxf(o.z, 0.f); o.w = fmaxf(o.w, 0.f);
        }
        *reinterpret_cast<float4*>(outp + (size_t)row * DD + tx * 4) = o;
    }
}

extern "C" void kernel_launch(void* const* d_in, const int* in_sizes, int n_in,
                              void* d_out, int out_size) {
    const float* x        = (const float*)d_in[0];
    const void* ei        = d_in[1];
    const float* Wl0      = (const float*)d_in[2];
    const float* bl0      = (const float*)d_in[3];
    const float* Wr0      = (const float*)d_in[4];
    const float* Wl1      = (const float*)d_in[5];
    const float* bl1      = (const float*)d_in[6];
    const float* Wr1      = (const float*)d_in[7];
    float* out = (float*)d_out;

    int E = in_sizes[1] / 2;

    int zeroBlocks = (NN * DD / 4 + 255) / 256;
    long long nThreads = ((long long)(E + EPB - 1) / EPB) * 16;
    int scatBlocks = (int)((nThreads + 255) / 256);
    int gemmBlocks = (NN + 63) / 64;

    detect_dtype<<<1, 1>>>((const long long*)ei);
    prep_weights<<<(2 * DD * DD + 255) / 256, 256>>>(Wl0, Wr0, Wl1, Wr1);

    // Layer 0
    zero_kernel<<<zeroBlocks, 256>>>(1);
    scatter_kernel<<<scatBlocks, 256>>>(x, ei, E, /*useH=*/0, /*doCount=*/1);
    gemm_combine<<<gemmBlocks, 256>>>(x, /*useH=*/0, /*useW1=*/0, bl0, out,
                                      /*writeH=*/1, /*doRelu=*/1);

    // Layer 1
    zero_kernel<<<zeroBlocks, 256>>>(0);
    scatter_kernel<<<scatBlocks, 256>>>(x, ei, E, /*useH=*/1, /*doCount=*/0);
    gemm_combine<<<gemmBlocks, 256>>>(x, /*useH=*/1, /*useW1=*/1, bl1, out,
                                      /*writeH=*/0, /*doRelu=*/0);
}

// round 5
// speedup vs baseline: 1.2192x; 1.1574x over previous
#include <cuda_runtime.h>
#include <cstdint>

#define NN 50000
#define DD 64
#define MAXE 1600000
#define SCAN_B 256

// Scratch (device globals; no allocations allowed)
__device__ __align__(16) float g_agg[NN * DD];     // normalized mean-agg buffer
__device__ __align__(16) float g_h[NN * DD];       // layer-0 output
__device__ __align__(16) float g_Wt0[2 * DD * DD]; // [k][j] pre-transposed weights
__device__ __align__(16) float g_Wt1[2 * DD * DD];
__device__ int g_is64;                             // edge-index dtype flag
__device__ int g_deg[NN];                          // in-degree (by dst)
__device__ int g_rowptr[NN];                       // CSR row starts (exclusive scan of deg)
__device__ int g_cur[NN];                          // fill cursors
__device__ int g_col[MAXE];                        // CSR column (src) indices
__device__ int g_bsum[(NN + SCAN_B - 1) / SCAN_B]; // scan block sums
__device__ int g_boff[(NN + SCAN_B - 1) / SCAN_B]; // scan block offsets

// ---- dtype detect: int64 indices < 50000 have zero hi-words ----
__global__ void detect_dtype(const long long* __restrict__ ei) {
    long long acc = 0;
#pragma unroll
    for (int i = 0; i < 8; i++) acc |= (ei[i] >> 32);
    g_is64 = (acc == 0) ? 1 : 0;
}

__device__ __forceinline__ int load_idx(const void* ei_raw, int pos) {
    if (g_is64) return (int)((const long long*)ei_raw)[pos];
    return ((const int*)ei_raw)[pos];
}

__global__ void prep_weights(const float* __restrict__ Wl0, const float* __restrict__ Wr0,
                             const float* __restrict__ Wl1, const float* __restrict__ Wr1) {
    int i = blockIdx.x * blockDim.x + threadIdx.x;
    if (i >= 2 * DD * DD) return;
    int k = i >> 6;
    int j = i & 63;
    g_Wt0[i] = (k < DD) ? Wl0[j * DD + k] : Wr0[j * DD + (k - DD)];
    g_Wt1[i] = (k < DD) ? Wl1[j * DD + k] : Wr1[j * DD + (k - DD)];
}

// ---- CSR build ----
__global__ void zero_deg() {
    int i = blockIdx.x * blockDim.x + threadIdx.x;
    if (i < NN) g_deg[i] = 0;
}

__global__ void histogram(const void* __restrict__ ei_raw, int E) {
    int e = blockIdx.x * blockDim.x + threadIdx.x;
    if (e >= E) return;
    int d = load_idx(ei_raw, E + e);
    atomicAdd(&g_deg[d], 1);
}

// exclusive scan, 3 kernels
__global__ void scan1() {
    __shared__ int sh[SCAN_B];
    int i = blockIdx.x * SCAN_B + threadIdx.x;
    int v = (i < NN) ? g_deg[i] : 0;
    sh[threadIdx.x] = v;
    __syncthreads();
#pragma unroll
    for (int off = 1; off < SCAN_B; off <<= 1) {
        int t = (threadIdx.x >= off) ? sh[threadIdx.x - off] : 0;
        __syncthreads();
        sh[threadIdx.x] += t;
        __syncthreads();
    }
    int incl = sh[threadIdx.x];
    if (i < NN) g_rowptr[i] = incl - v;
    if (threadIdx.x == SCAN_B - 1) g_bsum[blockIdx.x] = incl;
}

__global__ void scan2(int nblk) {
    __shared__ int sh[SCAN_B];
    int v = (threadIdx.x < nblk) ? g_bsum[threadIdx.x] : 0;
    sh[threadIdx.x] = v;
    __syncthreads();
#pragma unroll
    for (int off = 1; off < SCAN_B; off <<= 1) {
        int t = (threadIdx.x >= off) ? sh[threadIdx.x - off] : 0;
        __syncthreads();
        sh[threadIdx.x] += t;
        __syncthreads();
    }
    if (threadIdx.x < nblk) g_boff[threadIdx.x] = sh[threadIdx.x] - v;
}

__global__ void scan3() {
    int i = blockIdx.x * SCAN_B + threadIdx.x;
    if (i < NN) {
        int r = g_rowptr[i] + g_boff[blockIdx.x];
        g_rowptr[i] = r;
        g_cur[i] = r;
    }
}

__global__ void fill_csr(const void* __restrict__ ei_raw, int E) {
    int e = blockIdx.x * blockDim.x + threadIdx.x;
    if (e >= E) return;
    int s = load_idx(ei_raw, e);
    int d = load_idx(ei_raw, E + e);
    int pos = atomicAdd(&g_cur[d], 1);
    g_col[pos] = s;
}

// ---- pull-style aggregation: 16 threads per node, atomic-free ----
// Each group sequentially sums its neighbors' rows in registers (chunks of 4
// for MLP), normalizes by degree, writes once.
__global__ void aggregate(const float* __restrict__ x, int useH) {
    int gid = blockIdx.x * blockDim.x + threadIdx.x;
    int node = gid >> 4;
    int lane = gid & 15;
    if (node >= NN) return;
    const float* xin = useH ? g_h : x;

    int beg = g_rowptr[node];
    int deg = g_deg[node];

    float4 acc = make_float4(0.f, 0.f, 0.f, 0.f);
    int j = 0;
    for (; j + 4 <= deg; j += 4) {
        int i0 = __ldg(g_col + beg + j + 0);
        int i1 = __ldg(g_col + beg + j + 1);
        int i2 = __ldg(g_col + beg + j + 2);
        int i3 = __ldg(g_col + beg + j + 3);
        // 4 independent gathers in flight
        float4 v0 = __ldg(reinterpret_cast<const float4*>(xin + (size_t)i0 * DD) + lane);
        float4 v1 = __ldg(reinterpret_cast<const float4*>(xin + (size_t)i1 * DD) + lane);
        float4 v2 = __ldg(reinterpret_cast<const float4*>(xin + (size_t)i2 * DD) + lane);
        float4 v3 = __ldg(reinterpret_cast<const float4*>(xin + (size_t)i3 * DD) + lane);
        acc.x += v0.x; acc.y += v0.y; acc.z += v0.z; acc.w += v0.w;
        acc.x += v1.x; acc.y += v1.y; acc.z += v1.z; acc.w += v1.w;
        acc.x += v2.x; acc.y += v2.y; acc.z += v2.z; acc.w += v2.w;
        acc.x += v3.x; acc.y += v3.y; acc.z += v3.z; acc.w += v3.w;
    }
    for (; j < deg; j++) {
        int i0 = __ldg(g_col + beg + j);
        float4 v0 = __ldg(reinterpret_cast<const float4*>(xin + (size_t)i0 * DD) + lane);
        acc.x += v0.x; acc.y += v0.y; acc.z += v0.z; acc.w += v0.w;
    }
    float sc = 1.f / (float)max(deg, 1);
    acc.x *= sc; acc.y *= sc; acc.z *= sc; acc.w *= sc;
    reinterpret_cast<float4*>(g_agg + (size_t)node * DD)[lane] = acc;
}

// Fused: C[64 nodes][64 out] = A[64][128] * B[128][64] + bias (+ ReLU)
// A = [agg | xin] (agg already normalized), B = [Wl^T ; Wr^T].
__global__ __launch_bounds__(256) void gemm_combine(const float* __restrict__ x,
                                                    int useH, int useW1,
                                                    const float* __restrict__ bias,
                                                    float* __restrict__ dout,
                                                    int writeH, int doRelu) {
    __shared__ __align__(16) float sA[64 * 64];  // [k][m], k-half at a time
    __shared__ __align__(16) float sB[64 * 64];  // [k][j]
    const float* xin = useH ? g_h : x;
    const float* Wt = useW1 ? g_Wt1 : g_Wt0;
    float* outp = writeH ? g_h : dout;

    int t = threadIdx.x;
    int m0 = blockIdx.x * 64;
    int m = t & 63;
    int q = t >> 6;
    int node = m0 + m;

    int tx = t & 15;
    int ty = t >> 4;

    float acc[4][4];
#pragma unroll
    for (int i = 0; i < 4; i++)
#pragma unroll
        for (int j = 0; j < 4; j++) acc[i][j] = 0.f;

#pragma unroll
    for (int kt = 0; kt < 2; kt++) {
        const float4* Bsrc = reinterpret_cast<const float4*>(Wt + kt * 4096);
#pragma unroll
        for (int f = 0; f < 4; f++)
            reinterpret_cast<float4*>(sB)[f * 256 + t] = Bsrc[f * 256 + t];

        const float* srcRow = (kt == 0) ? (g_agg + (size_t)node * DD)
                                        : (xin + (size_t)node * DD);
        int kbase = q * 16;
#pragma unroll
        for (int f = 0; f < 4; f++) {
            float4 v = make_float4(0.f, 0.f, 0.f, 0.f);
            if (node < NN)
                v = *reinterpret_cast<const float4*>(srcRow + kbase + f * 4);
            int k = kbase + f * 4;
            sA[(k + 0) * 64 + m] = v.x;
            sA[(k + 1) * 64 + m] = v.y;
            sA[(k + 2) * 64 + m] = v.z;
            sA[(k + 3) * 64 + m] = v.w;
        }
        __syncthreads();

#pragma unroll 8
        for (int k = 0; k < 64; k++) {
            float4 a = *reinterpret_cast<const float4*>(sA + k * 64 + ty * 4);
            float4 b = *reinterpret_cast<const float4*>(sB + k * 64 + tx * 4);
            acc[0][0] += a.x * b.x; acc[0][1] += a.x * b.y; acc[0][2] += a.x * b.z; acc[0][3] += a.x * b.w;
            acc[1][0] += a.y * b.x; acc[1][1] += a.y * b.y; acc[1][2] += a.y * b.z; acc[1][3] += a.y * b.w;
            acc[2][0] += a.z * b.x; acc[2][1] += a.z * b.y; acc[2][2] += a.z * b.z; acc[2][3] += a.z * b.w;
            acc[3][0] += a.w * b.x; acc[3][1] += a.w * b.y; acc[3][2] += a.w * b.z; acc[3][3] += a.w * b.w;
        }
        __syncthreads();
    }

    float4 bv = *reinterpret_cast<const float4*>(bias + tx * 4);
#pragma unroll
    for (int i = 0; i < 4; i++) {
        int row = m0 + ty * 4 + i;
        if (row >= NN) continue;
        float4 o;
        o.x = acc[i][0] + bv.x;
        o.y = acc[i][1] + bv.y;
        o.z = acc[i][2] + bv.z;
        o.w = acc[i][3] + bv.w;
        if (doRelu) {
            o.x = fmaxf(o.x, 0.f); o.y = fmaxf(o.y, 0.f);
            o.z = fmaxf(o.z, 0.f); o.w = fmaxf(o.w, 0.f);
        }
        *reinterpret_cast<float4*>(outp + (size_t)row * DD + tx * 4) = o;
    }
}

extern "C" void kernel_launch(void* const* d_in, const int* in_sizes, int n_in,
                              void* d_out, int out_size) {
    const float* x        = (const float*)d_in[0];
    const void* ei        = d_in[1];
    const float* Wl0      = (const float*)d_in[2];
    const float* bl0      = (const float*)d_in[3];
    const float* Wr0      = (const float*)d_in[4];
    const float* Wl1      = (const float*)d_in[5];
    const float* bl1      = (const float*)d_in[6];
    const float* Wr1      = (const float*)d_in[7];
    float* out = (float*)d_out;

    int E = in_sizes[1] / 2;

    int nblk = (NN + SCAN_B - 1) / SCAN_B;          // 196
    int edgeBlocks = (E + 255) / 256;
    int aggBlocks = (NN * 16 + 255) / 256;
    int gemmBlocks = (NN + 63) / 64;

    detect_dtype<<<1, 1>>>((const long long*)ei);
    prep_weights<<<(2 * DD * DD + 255) / 256, 256>>>(Wl0, Wr0, Wl1, Wr1);

    // CSR build (shared by both layers)
    zero_deg<<<nblk, SCAN_B>>>();
    histogram<<<edgeBlocks, 256>>>(ei, E);
    scan1<<<nblk, SCAN_B>>>();
    scan2<<<1, SCAN_B>>>(nblk);
    scan3<<<nblk, SCAN_B>>>();
    fill_csr<<<edgeBlocks, 256>>>(ei, E);

    // Layer 0
    aggregate<<<aggBlocks, 256>>>(x, /*useH=*/0);
    gemm_combine<<<gemmBlocks, 256>>>(x, /*useH=*/0, /*useW1=*/0, bl0, out,
                                      /*writeH=*/1, /*doRelu=*/1);

    // Layer 1
    aggregate<<<aggBlocks, 256>>>(x, /*useH=*/1);
    gemm_combine<<<gemmBlocks, 256>>>(x, /*useH=*/1, /*useW1=*/1, bl1, out,
                                      /*writeH=*/0, /*doRelu=*/0);
}